// round 1
// baseline (speedup 1.0000x reference)
#include <cuda_runtime.h>

#define HIDDEN 1024
#define NHEADS 16
#define HDIM 64
#define BATCH 2
#define SEQ 2048
#define SCALE 0.03125f  /* HIDDEN^-0.5 = 1/32 */

// scratch (allocation-free rule: __device__ globals)
__device__ float g_q[BATCH * NHEADS * SEQ * HDIM];
__device__ float g_k[BATCH * NHEADS * SEQ * HDIM];
__device__ float g_v[BATCH * NHEADS * SEQ * HDIM];

// ---------------------------------------------------------------------------
// Kernel 1: fused QKV projection.
// hidden [4096 x 1024] (row-major)  x  W[h][1024 x 192]  -> q/k/v [bh][n][64]
// Tile: BM=128, BN=64, BK=8; 256 threads; 8x4 microtile per thread.
// blockIdx.x selects the 64-wide column slice (0=Q, 1=K, 2=V of a head).
// ---------------------------------------------------------------------------
__global__ __launch_bounds__(256) void qkv_kernel(const float* __restrict__ hidden,
                                                  const float* __restrict__ W) {
    __shared__ float As[8 * 128];   // transposed: As[k][m]
    __shared__ float Bs[8 * 64];    // Bs[k][c]

    const int h     = blockIdx.z;
    const int m0    = blockIdx.y * 128;
    const int cbase = blockIdx.x * 64;   // 0, 64, 128 within the 192 cols of a head
    const int tid   = threadIdx.x;
    const int tx    = tid & 15;          // 0..15 -> 4 cols each
    const int ty    = tid >> 4;          // 0..15 -> 8 rows each

    const float* Wh = W + (size_t)h * HIDDEN * 192;

    // A-load mapping: 128 rows x 8 k, float4 per thread
    const int lr = tid >> 1;             // 0..127
    const int lk = (tid & 1) * 4;        // 0 or 4
    // B-load mapping: 8 k x 64 c, 2 scalars per thread
    const int bk = tid >> 6;             // 0..3
    const int bc = tid & 63;             // 0..63

    float acc[8][4] = {};

    for (int k0 = 0; k0 < HIDDEN; k0 += 8) {
        float4 av = *(const float4*)&hidden[(size_t)(m0 + lr) * HIDDEN + k0 + lk];
        As[(lk + 0) * 128 + lr] = av.x;
        As[(lk + 1) * 128 + lr] = av.y;
        As[(lk + 2) * 128 + lr] = av.z;
        As[(lk + 3) * 128 + lr] = av.w;
        Bs[bk * 64 + bc]       = Wh[(size_t)(k0 + bk) * 192 + cbase + bc];
        Bs[(bk + 4) * 64 + bc] = Wh[(size_t)(k0 + bk + 4) * 192 + cbase + bc];
        __syncthreads();

#pragma unroll
        for (int kk = 0; kk < 8; kk++) {
            float4 a0 = *(float4*)&As[kk * 128 + ty * 8];
            float4 a1 = *(float4*)&As[kk * 128 + ty * 8 + 4];
            float4 bv = *(float4*)&Bs[kk * 64 + tx * 4];
            float a[8] = {a0.x, a0.y, a0.z, a0.w, a1.x, a1.y, a1.z, a1.w};
            float bb[4] = {bv.x, bv.y, bv.z, bv.w};
#pragma unroll
            for (int i = 0; i < 8; i++)
#pragma unroll
                for (int j = 0; j < 4; j++)
                    acc[i][j] += a[i] * bb[j];
        }
        __syncthreads();
    }

    // epilogue: whole block maps to exactly one of Q/K/V
    float* dst = (cbase == 0) ? g_q : (cbase == 64 ? g_k : g_v);
#pragma unroll
    for (int i = 0; i < 8; i++) {
        int m = m0 + ty * 8 + i;
        int b = m >> 11;         // /2048
        int n = m & 2047;
        float4 v4 = make_float4(acc[i][0], acc[i][1], acc[i][2], acc[i][3]);
        *(float4*)&dst[(((size_t)(b * NHEADS + h) * SEQ) + n) * HDIM + tx * 4] = v4;
    }
}

// ---------------------------------------------------------------------------
// Kernel 2: SIMT flash attention (fp32).
// Q-block = 32 rows, KV-block = 64 keys, 256 threads.
// Thread (ty,tx): rows {ty*2, ty*2+1}, cols {tx*4..tx*4+3}.
// Kt stored transposed with pad 65 (conflict-free); P reuses the Kt buffer.
// Row softmax state lives in registers, reduced over the 16-lane row group.
// ---------------------------------------------------------------------------
__global__ __launch_bounds__(256) void flash_kernel(const int* __restrict__ mask,
                                                    float* __restrict__ out) {
    __shared__ float Qs[32 * 64];     // 8 KB (holds Q * SCALE)
    __shared__ float KtP[64 * 65];    // 16.25 KB: Kt[d][key], later P[r][key]
    __shared__ float Vs[64 * 64];     // 16 KB: V[key][d]
    __shared__ float mflag[64];

    const int bh  = blockIdx.y;
    const int b   = bh >> 4;
    const int h   = bh & 15;
    const int q0  = blockIdx.x * 32;
    const int tid = threadIdx.x;
    const int tx  = tid & 15;
    const int ty  = tid >> 4;
    const int r0  = ty * 2;
    const int r1  = ty * 2 + 1;

    const float* Qg = g_q + (size_t)bh * SEQ * HDIM;
    const float* Kg = g_k + (size_t)bh * SEQ * HDIM;
    const float* Vg = g_v + (size_t)bh * SEQ * HDIM;

#pragma unroll
    for (int it = 0; it < 8; it++) {
        int g = tid + 256 * it;                        // 0..2047
        Qs[g] = Qg[(size_t)(q0 + (g >> 6)) * HDIM + (g & 63)] * SCALE;
    }

    float mrow0 = -1e30f, mrow1 = -1e30f;
    float l0 = 0.f, l1 = 0.f;
    float acc0[4] = {}, acc1[4] = {};

    for (int j0 = 0; j0 < SEQ; j0 += 64) {
        __syncthreads();   // previous iteration's P/V reads complete

        // load Kt (transposed, stride 65) + V (direct) + mask
#pragma unroll
        for (int it = 0; it < 16; it++) {
            int g = tid + 256 * it;                    // 0..4095
            int c = g >> 6, d = g & 63;
            KtP[d * 65 + c] = Kg[(size_t)(j0 + c) * HDIM + d];
            Vs[g] = Vg[(size_t)j0 * HDIM + g];
        }
        if (tid < 64) mflag[tid] = (mask[b * SEQ + j0 + tid] != 0) ? 1.f : 0.f;
        __syncthreads();

        // S = (Q*SCALE) @ K^T, 2x4 per thread
        float s0[4] = {}, s1[4] = {};
#pragma unroll 4
        for (int d = 0; d < 64; d++) {
            float qa = Qs[r0 * 64 + d];
            float qb = Qs[r1 * 64 + d];
#pragma unroll
            for (int j = 0; j < 4; j++) {
                float kv = KtP[d * 65 + tx * 4 + j];
                s0[j] += qa * kv;
                s1[j] += qb * kv;
            }
        }
        __syncthreads();   // Kt reads done; buffer reusable as P

        float mf[4];
#pragma unroll
        for (int j = 0; j < 4; j++) mf[j] = mflag[tx * 4 + j];
#pragma unroll
        for (int j = 0; j < 4; j++) {
            if (mf[j] == 0.f) { s0[j] = -1e30f; s1[j] = -1e30f; }
        }

        // row max (4 local + 16-lane shfl tree)
        float mb0 = fmaxf(fmaxf(s0[0], s0[1]), fmaxf(s0[2], s0[3]));
        float mb1 = fmaxf(fmaxf(s1[0], s1[1]), fmaxf(s1[2], s1[3]));
#pragma unroll
        for (int o = 8; o >= 1; o >>= 1) {
            mb0 = fmaxf(mb0, __shfl_xor_sync(0xffffffffu, mb0, o));
            mb1 = fmaxf(mb1, __shfl_xor_sync(0xffffffffu, mb1, o));
        }
        float mn0 = fmaxf(mrow0, mb0);
        float mn1 = fmaxf(mrow1, mb1);
        float f0 = __expf(mrow0 - mn0);
        float f1 = __expf(mrow1 - mn1);

        float ps0 = 0.f, ps1 = 0.f;
#pragma unroll
        for (int j = 0; j < 4; j++) {
            float p0 = __expf(s0[j] - mn0) * mf[j];
            float p1 = __expf(s1[j] - mn1) * mf[j];
            KtP[r0 * 65 + tx * 4 + j] = p0;
            KtP[r1 * 65 + tx * 4 + j] = p1;
            ps0 += p0; ps1 += p1;
        }
#pragma unroll
        for (int o = 8; o >= 1; o >>= 1) {
            ps0 += __shfl_xor_sync(0xffffffffu, ps0, o);
            ps1 += __shfl_xor_sync(0xffffffffu, ps1, o);
        }
        l0 = l0 * f0 + ps0;
        l1 = l1 * f1 + ps1;
        mrow0 = mn0; mrow1 = mn1;
#pragma unroll
        for (int j = 0; j < 4; j++) { acc0[j] *= f0; acc1[j] *= f1; }
        __syncthreads();   // P visible to everyone

        // O += P @ V
#pragma unroll 4
        for (int k = 0; k < 64; k++) {
            float p0 = KtP[r0 * 65 + k];
            float p1 = KtP[r1 * 65 + k];
            float4 vv = *(float4*)&Vs[k * 64 + tx * 4];
            acc0[0] += p0 * vv.x; acc0[1] += p0 * vv.y;
            acc0[2] += p0 * vv.z; acc0[3] += p0 * vv.w;
            acc1[0] += p1 * vv.x; acc1[1] += p1 * vv.y;
            acc1[2] += p1 * vv.z; acc1[3] += p1 * vv.w;
        }
    }

    float inv0 = 1.f / l0;
    float inv1 = 1.f / l1;
    int n0 = q0 + r0, n1 = q0 + r1;
    float4 o0 = make_float4(acc0[0] * inv0, acc0[1] * inv0, acc0[2] * inv0, acc0[3] * inv0);
    float4 o1 = make_float4(acc1[0] * inv1, acc1[1] * inv1, acc1[2] * inv1, acc1[3] * inv1);
    *(float4*)&out[((size_t)(b * SEQ + n0) * HIDDEN) + h * HDIM + tx * 4] = o0;
    *(float4*)&out[((size_t)(b * SEQ + n1) * HIDDEN) + h * HDIM + tx * 4] = o1;
}

// ---------------------------------------------------------------------------
extern "C" void kernel_launch(void* const* d_in, const int* in_sizes, int n_in,
                              void* d_out, int out_size) {
    const float* hidden = (const float*)d_in[0];   // [2, 2048, 1024] f32
    const int*   amask  = (const int*)d_in[1];     // [2, 2048] i32
    const float* W      = (const float*)d_in[2];   // [16, 1024, 192] f32
    float* out = (float*)d_out;                    // [2, 2048, 1024] f32

    (void)in_sizes; (void)n_in; (void)out_size;

    // QKV projection: grid (192/64, 4096/128, heads)
    qkv_kernel<<<dim3(3, 32, 16), 256>>>(hidden, W);
    // Flash attention: grid (2048/32 q-blocks, b*h)
    flash_kernel<<<dim3(64, 32), 256>>>(amask, out);
}

// round 2
// speedup vs baseline: 4.1568x; 4.1568x over previous
#include <cuda_runtime.h>
#include <cstdint>

#define HIDDEN 1024
#define NHEADS 16
#define HDIM 64
#define BATCH 2
#define SEQ 2048
#define SCALE 0.03125f  /* HIDDEN^-0.5 */

// scratch (allocation-free rule: __device__ globals)
__device__ float g_q[BATCH * NHEADS * SEQ * HDIM];
__device__ float g_k[BATCH * NHEADS * SEQ * HDIM];
__device__ float g_v[BATCH * NHEADS * SEQ * HDIM];

// round-to-nearest fp32 -> tf32 (unbiased; avoids HMMA truncation bias)
__device__ __forceinline__ float to_tf32(float x) {
    unsigned u;
    asm("cvt.rna.tf32.f32 %0, %1;" : "=r"(u) : "f"(x));
    return __uint_as_float(u);
}

// D += A*B, m16n8k8, tf32 inputs, f32 accumulate
__device__ __forceinline__ void mma_tf32(float c[4], const unsigned a[4], const unsigned b[2]) {
    asm volatile(
        "mma.sync.aligned.m16n8k8.row.col.f32.tf32.tf32.f32 "
        "{%0,%1,%2,%3},{%4,%5,%6,%7},{%8,%9},{%0,%1,%2,%3};\n"
        : "+f"(c[0]), "+f"(c[1]), "+f"(c[2]), "+f"(c[3])
        : "r"(a[0]), "r"(a[1]), "r"(a[2]), "r"(a[3]), "r"(b[0]), "r"(b[1]));
}

// ---------------------------------------------------------------------------
// Kernel 1: fused QKV projection (tf32 tensor-core GEMM).
// C[4096 x 192/head] = hidden[4096 x 1024] x W[h][1024 x 192]
// Block: BM=128, BN=64 (one of q/k/v slice), BK=32, 256 threads (8 warps).
// Warp tile 32x32 = 2 m16 x 4 n8 tiles.
// ---------------------------------------------------------------------------
__global__ __launch_bounds__(256) void qkv_kernel(const float* __restrict__ hidden,
                                                  const float* __restrict__ W) {
    __shared__ float As[128 * 36];   // [m][k], stride 36 -> conflict-free frags
    __shared__ float Bs[32 * 68];    // [k][n], stride 68

    const int h     = blockIdx.z;
    const int m0    = blockIdx.y * 128;
    const int cbase = blockIdx.x * 64;   // 0 (Q), 64 (K), 128 (V)
    const int tid   = threadIdx.x;
    const int wid   = tid >> 5, lane = tid & 31;
    const int g     = lane >> 2, tg = lane & 3;
    const int wy    = wid & 3;   // m offset wy*32
    const int wx    = wid >> 2;  // n offset wx*32

    const float* Wh = W + (size_t)h * HIDDEN * 192;

    const int ar = tid >> 3;         // A rows ar + 32*i
    const int ak = (tid & 7) * 4;
    const int br = tid >> 4;         // B rows br, br+16
    const int bc = (tid & 15) * 4;

    float acc[2][4][4] = {};

    for (int k0 = 0; k0 < HIDDEN; k0 += 32) {
        float4 a[4], bv[2];
#pragma unroll
        for (int i = 0; i < 4; i++)
            a[i] = *(const float4*)&hidden[(size_t)(m0 + ar + 32 * i) * HIDDEN + k0 + ak];
        bv[0] = *(const float4*)&Wh[(size_t)(k0 + br) * 192 + cbase + bc];
        bv[1] = *(const float4*)&Wh[(size_t)(k0 + br + 16) * 192 + cbase + bc];

        __syncthreads();   // previous tile's frag reads done
#pragma unroll
        for (int i = 0; i < 4; i++) {
            float* d = &As[(ar + 32 * i) * 36 + ak];
            d[0] = to_tf32(a[i].x); d[1] = to_tf32(a[i].y);
            d[2] = to_tf32(a[i].z); d[3] = to_tf32(a[i].w);
        }
        {
            float* d0 = &Bs[br * 68 + bc];
            d0[0] = to_tf32(bv[0].x); d0[1] = to_tf32(bv[0].y);
            d0[2] = to_tf32(bv[0].z); d0[3] = to_tf32(bv[0].w);
            float* d1 = &Bs[(br + 16) * 68 + bc];
            d1[0] = to_tf32(bv[1].x); d1[1] = to_tf32(bv[1].y);
            d1[2] = to_tf32(bv[1].z); d1[3] = to_tf32(bv[1].w);
        }
        __syncthreads();

#pragma unroll
        for (int ks = 0; ks < 4; ks++) {
            const int kk = ks * 8;
            unsigned af[2][4];
#pragma unroll
            for (int mt = 0; mt < 2; mt++) {
                const int row = wy * 32 + mt * 16;
                af[mt][0] = __float_as_uint(As[(row + g) * 36 + kk + tg]);
                af[mt][1] = __float_as_uint(As[(row + g + 8) * 36 + kk + tg]);
                af[mt][2] = __float_as_uint(As[(row + g) * 36 + kk + tg + 4]);
                af[mt][3] = __float_as_uint(As[(row + g + 8) * 36 + kk + tg + 4]);
            }
#pragma unroll
            for (int nt = 0; nt < 4; nt++) {
                const int col = wx * 32 + nt * 8 + g;
                unsigned bf[2];
                bf[0] = __float_as_uint(Bs[(kk + tg) * 68 + col]);
                bf[1] = __float_as_uint(Bs[(kk + tg + 4) * 68 + col]);
#pragma unroll
                for (int mt = 0; mt < 2; mt++)
                    mma_tf32(acc[mt][nt], af[mt], bf);
            }
        }
    }

    float* dst = (cbase == 0) ? g_q : (cbase == 64 ? g_k : g_v);
#pragma unroll
    for (int mt = 0; mt < 2; mt++) {
        const int row = m0 + wy * 32 + mt * 16 + g;
        const int b = row >> 11, n = row & 2047;
#pragma unroll
        for (int nt = 0; nt < 4; nt++) {
            const int col = wx * 32 + nt * 8 + 2 * tg;
            const size_t base = (((size_t)(b * NHEADS + h)) * SEQ + n) * HDIM + col;
            *(float2*)&dst[base] = make_float2(acc[mt][nt][0], acc[mt][nt][1]);
            *(float2*)&dst[base + 8 * HDIM] = make_float2(acc[mt][nt][2], acc[mt][nt][3]);
        }
    }
}

// ---------------------------------------------------------------------------
// Kernel 2: flash attention on tensor cores (tf32).
// BQ = BKV = 64, 256 threads / 8 warps. Warp tile m16 x n32 (wy in [0,4), wx in [0,2)).
// S = (Q*SCALE) K^T via mma; online softmax (per-quad stats + 2-warp smem
// exchange); P overwrites the K smem buffer; O += P V via mma.
// ---------------------------------------------------------------------------
__global__ __launch_bounds__(256) void flash_kernel(const int* __restrict__ mask,
                                                    float* __restrict__ out) {
    extern __shared__ float dsm[];
    float* Qs = dsm;               // [64][68] tf32 (Q*SCALE)
    float* KP = dsm + 64 * 68;     // [64][68] K^T source rows, then P
    float* Vs = dsm + 2 * 64 * 68; // [64][72]
    __shared__ float redmax[2][64];
    __shared__ float redsum[2][64];
    __shared__ float mflag[64];

    const int bh = blockIdx.y, b = bh >> 4, h = bh & 15;
    const int q0 = blockIdx.x * 64;
    const int tid = threadIdx.x, wid = tid >> 5, lane = tid & 31;
    const int g = lane >> 2, tg = lane & 3;
    const int wy = wid & 3, wx = wid >> 2;
    const int row0 = wy * 16 + g, row1 = row0 + 8;

    const float* Qg = g_q + (size_t)bh * SEQ * HDIM;
    const float* Kg = g_k + (size_t)bh * SEQ * HDIM;
    const float* Vg = g_v + (size_t)bh * SEQ * HDIM;

    const int lr = tid >> 4, lc = (tid & 15) * 4;

    // Q tile (scaled + tf32-rounded), loaded once
#pragma unroll
    for (int i = 0; i < 4; i++) {
        float4 v = *(const float4*)&Qg[(size_t)(q0 + lr + 16 * i) * HDIM + lc];
        float* d = &Qs[(lr + 16 * i) * 68 + lc];
        d[0] = to_tf32(v.x * SCALE); d[1] = to_tf32(v.y * SCALE);
        d[2] = to_tf32(v.z * SCALE); d[3] = to_tf32(v.w * SCALE);
    }

    float m0r = -1e30f, m1r = -1e30f, l0r = 0.f, l1r = 0.f;
    float oreg[4][4] = {};

    for (int j0 = 0; j0 < SEQ; j0 += 64) {
        // prefetch K/V/mask to regs
        float4 kv4[4], vv4[4];
#pragma unroll
        for (int i = 0; i < 4; i++) {
            kv4[i] = *(const float4*)&Kg[(size_t)(j0 + lr + 16 * i) * HDIM + lc];
            vv4[i] = *(const float4*)&Vg[(size_t)(j0 + lr + 16 * i) * HDIM + lc];
        }
        float mfv = 0.f;
        if (tid < 64) mfv = (mask[b * SEQ + j0 + tid] != 0) ? 1.f : 0.f;

        __syncthreads();   // previous iteration's PV frag reads done
#pragma unroll
        for (int i = 0; i < 4; i++) {
            float* dk = &KP[(lr + 16 * i) * 68 + lc];
            dk[0] = to_tf32(kv4[i].x); dk[1] = to_tf32(kv4[i].y);
            dk[2] = to_tf32(kv4[i].z); dk[3] = to_tf32(kv4[i].w);
            float* dv = &Vs[(lr + 16 * i) * 72 + lc];
            dv[0] = to_tf32(vv4[i].x); dv[1] = to_tf32(vv4[i].y);
            dv[2] = to_tf32(vv4[i].z); dv[3] = to_tf32(vv4[i].w);
        }
        if (tid < 64) mflag[tid] = mfv;
        __syncthreads();

        // ---- S = Q K^T ----
        float sreg[4][4] = {};
#pragma unroll
        for (int ks = 0; ks < 8; ks++) {
            const int kk = ks * 8;
            unsigned af[4];
            af[0] = __float_as_uint(Qs[row0 * 68 + kk + tg]);
            af[1] = __float_as_uint(Qs[row1 * 68 + kk + tg]);
            af[2] = __float_as_uint(Qs[row0 * 68 + kk + tg + 4]);
            af[3] = __float_as_uint(Qs[row1 * 68 + kk + tg + 4]);
#pragma unroll
            for (int nt = 0; nt < 4; nt++) {
                const int col = wx * 32 + nt * 8 + g;
                unsigned bf[2];
                bf[0] = __float_as_uint(KP[col * 68 + kk + tg]);
                bf[1] = __float_as_uint(KP[col * 68 + kk + tg + 4]);
                mma_tf32(sreg[nt], af, bf);
            }
        }

        // ---- mask + row max ----
        float fl[4][2];
        float mx0 = -1e30f, mx1 = -1e30f;
#pragma unroll
        for (int nt = 0; nt < 4; nt++) {
            const int cb = wx * 32 + nt * 8 + 2 * tg;
            fl[nt][0] = mflag[cb]; fl[nt][1] = mflag[cb + 1];
            if (fl[nt][0] == 0.f) { sreg[nt][0] = -1e30f; sreg[nt][2] = -1e30f; }
            if (fl[nt][1] == 0.f) { sreg[nt][1] = -1e30f; sreg[nt][3] = -1e30f; }
            mx0 = fmaxf(mx0, fmaxf(sreg[nt][0], sreg[nt][1]));
            mx1 = fmaxf(mx1, fmaxf(sreg[nt][2], sreg[nt][3]));
        }
        mx0 = fmaxf(mx0, __shfl_xor_sync(0xffffffffu, mx0, 1));
        mx0 = fmaxf(mx0, __shfl_xor_sync(0xffffffffu, mx0, 2));
        mx1 = fmaxf(mx1, __shfl_xor_sync(0xffffffffu, mx1, 1));
        mx1 = fmaxf(mx1, __shfl_xor_sync(0xffffffffu, mx1, 2));
        if (tg == 0) { redmax[wx][row0] = mx0; redmax[wx][row1] = mx1; }
        __syncthreads();   // also: all Ks frag reads done -> KP reusable as P

        const float mb0 = fmaxf(redmax[0][row0], redmax[1][row0]);
        const float mb1 = fmaxf(redmax[0][row1], redmax[1][row1]);
        const float mn0 = fmaxf(m0r, mb0), mn1 = fmaxf(m1r, mb1);
        const float f0 = __expf(m0r - mn0), f1 = __expf(m1r - mn1);
        m0r = mn0; m1r = mn1;

        // ---- P = exp(S - m), row sums, write P to smem ----
        float ps0 = 0.f, ps1 = 0.f;
#pragma unroll
        for (int nt = 0; nt < 4; nt++) {
            const int cb = wx * 32 + nt * 8 + 2 * tg;
            float p0 = __expf(sreg[nt][0] - mn0) * fl[nt][0];
            float p1 = __expf(sreg[nt][1] - mn0) * fl[nt][1];
            float p2 = __expf(sreg[nt][2] - mn1) * fl[nt][0];
            float p3 = __expf(sreg[nt][3] - mn1) * fl[nt][1];
            ps0 += p0 + p1; ps1 += p2 + p3;
            KP[row0 * 68 + cb]     = to_tf32(p0);
            KP[row0 * 68 + cb + 1] = to_tf32(p1);
            KP[row1 * 68 + cb]     = to_tf32(p2);
            KP[row1 * 68 + cb + 1] = to_tf32(p3);
        }
        ps0 += __shfl_xor_sync(0xffffffffu, ps0, 1);
        ps0 += __shfl_xor_sync(0xffffffffu, ps0, 2);
        ps1 += __shfl_xor_sync(0xffffffffu, ps1, 1);
        ps1 += __shfl_xor_sync(0xffffffffu, ps1, 2);
        if (tg == 0) { redsum[wx][row0] = ps0; redsum[wx][row1] = ps1; }

        // rescale O accumulators while sums propagate
#pragma unroll
        for (int nt = 0; nt < 4; nt++) {
            oreg[nt][0] *= f0; oreg[nt][1] *= f0;
            oreg[nt][2] *= f1; oreg[nt][3] *= f1;
        }
        __syncthreads();   // P + redsum visible

        l0r = l0r * f0 + redsum[0][row0] + redsum[1][row0];
        l1r = l1r * f1 + redsum[0][row1] + redsum[1][row1];

        // ---- O += P V ----
#pragma unroll
        for (int ks = 0; ks < 8; ks++) {
            const int kk = ks * 8;
            unsigned af[4];
            af[0] = __float_as_uint(KP[row0 * 68 + kk + tg]);
            af[1] = __float_as_uint(KP[row1 * 68 + kk + tg]);
            af[2] = __float_as_uint(KP[row0 * 68 + kk + tg + 4]);
            af[3] = __float_as_uint(KP[row1 * 68 + kk + tg + 4]);
#pragma unroll
            for (int nt = 0; nt < 4; nt++) {
                const int col = wx * 32 + nt * 8 + g;
                unsigned bf[2];
                bf[0] = __float_as_uint(Vs[(kk + tg) * 72 + col]);
                bf[1] = __float_as_uint(Vs[(kk + tg + 4) * 72 + col]);
                mma_tf32(oreg[nt], af, bf);
            }
        }
    }

    const float inv0 = 1.f / l0r, inv1 = 1.f / l1r;
#pragma unroll
    for (int nt = 0; nt < 4; nt++) {
        const int col = h * HDIM + wx * 32 + nt * 8 + 2 * tg;
        const size_t o0 = ((size_t)(b * SEQ + q0 + row0)) * HIDDEN + col;
        const size_t o1 = ((size_t)(b * SEQ + q0 + row1)) * HIDDEN + col;
        *(float2*)&out[o0] = make_float2(oreg[nt][0] * inv0, oreg[nt][1] * inv0);
        *(float2*)&out[o1] = make_float2(oreg[nt][2] * inv1, oreg[nt][3] * inv1);
    }
}

// ---------------------------------------------------------------------------
extern "C" void kernel_launch(void* const* d_in, const int* in_sizes, int n_in,
                              void* d_out, int out_size) {
    const float* hidden = (const float*)d_in[0];   // [2, 2048, 1024] f32
    const int*   amask  = (const int*)d_in[1];     // [2, 2048] i32
    const float* W      = (const float*)d_in[2];   // [16, 1024, 192] f32
    float* out = (float*)d_out;                    // [2, 2048, 1024] f32
    (void)in_sizes; (void)n_in; (void)out_size;

    const int flash_smem = (64 * 68 * 2 + 64 * 72) * sizeof(float);  // 53248 B
    cudaFuncSetAttribute(flash_kernel, cudaFuncAttributeMaxDynamicSharedMemorySize,
                         flash_smem);

    qkv_kernel<<<dim3(3, 32, 16), 256>>>(hidden, W);
    flash_kernel<<<dim3(SEQ / 64, BATCH * NHEADS), 256, flash_smem>>>(amask, out);
}